// round 15
// baseline (speedup 1.0000x reference)
#include <cuda_runtime.h>
#include <cuda_bf16.h>
#include <math.h>
#include <stdint.h>

#define TT 64
#define BB 32
#define SS 64
#define HH 1024
#define NBLK 128

typedef __nv_bfloat16 bf16;

// ---------------- static device scratch (no allocations) ----------------
// Weight fragments (uint32): [rowtile16][kstep][sel hi/lo][lane(32)][reg(4)]
// g_w0/g_w1 rows use 4-ROWTILE GATE PERMUTATION: rowtile rt=4*blk+gate holds gate
// `gate` of hh [blk*16, blk*16+16).
__device__ uint32_t g_w0[(size_t)256 * 192 * 2 * 128];  // ks 0-63 ih0-emb, 64-127 ih0-feed, 128-191 hh0
__device__ uint32_t g_w1[(size_t)256 * 128 * 2 * 128];  // ks 0-63 ih1(h0), 64-127 hh1(h1)
__device__ uint32_t g_wq[(size_t)64 * 64 * 2 * 128];    // W_in
__device__ uint32_t g_wo[(size_t)64 * 128 * 2 * 128];   // W_out: ks 0-63 cvec, 64-127 h1

// Activation B-fragments: per 1024-k vector: [kstep(64)][sel(2)][ntile(4)][lane(32)][reg(2)]
__device__ uint32_t g_embx[(size_t)TT * 32768];
__device__ uint32_t g_h0x[2][32768];   // double-buffered
__device__ uint32_t g_h1x[2][32768];
__device__ uint32_t g_feedx[32768];
__device__ uint32_t g_cvx[32768];

__device__ float g_ge[(size_t)TT * 4096 * 32];  // precomputed W_ih0_emb @ emb_t (fragment-row order)
__device__ float g_c0T[HH * BB];
__device__ float g_c1T[HH * BB];
__device__ float g_qf[HH * BB];                 // [b][row]
__device__ float g_pp[64][2048];                // cross-block partials (pair slots)

// epoch flags (32B padded, monotonic)
__device__ unsigned g_barA[128 * 8];
__device__ unsigned g_barB[128 * 8];
__device__ unsigned g_flagP1[64 * 8];
__device__ unsigned g_flagP2[64 * 8];
__device__ unsigned g_flagPO[32 * 8];
__device__ unsigned g_flagQ[32 * 8];
__device__ unsigned g_flagCV[32 * 8];
__device__ unsigned g_flagF[32 * 8];

// ---------------- helpers ----------------
__device__ __forceinline__ float sigm(float x) { return 1.f / (1.f + expf(-x)); }

__device__ __forceinline__ void store_x(bf16* base, int hh, int b, float v) {
    int kstep = hh >> 4, kk = hh & 15;
    int ntile = b >> 3, gid = b & 7;
    int reg = kk >> 3, krem = kk & 7, tig = krem >> 1, half = krem & 1;
    int lane = gid * 4 + tig;
    bf16 hi = __float2bfloat16(v);
    bf16 lo = __float2bfloat16(v - __bfloat162float(hi));
    size_t i0 = ((((size_t)kstep * 2 + 0) * 4 + ntile) * 64 + lane * 2 + reg) * 2 + half;
    size_t i1 = ((((size_t)kstep * 2 + 1) * 4 + ntile) * 64 + lane * 2 + reg) * 2 + half;
    base[i0] = hi;
    base[i1] = lo;
}

__device__ __forceinline__ void mma_bf16(float* d, const uint32_t* a, uint32_t b0, uint32_t b1) {
    asm volatile(
        "mma.sync.aligned.m16n8k16.row.col.f32.bf16.bf16.f32 "
        "{%0,%1,%2,%3}, {%4,%5,%6,%7}, {%8,%9}, {%0,%1,%2,%3};"
        : "+f"(d[0]), "+f"(d[1]), "+f"(d[2]), "+f"(d[3])
        : "r"(a[0]), "r"(a[1]), "r"(a[2]), "r"(a[3]), "r"(b0), "r"(b1));
}

__device__ __forceinline__ void flag_set(unsigned* f, int slot, unsigned e) {
    __syncthreads();
    __threadfence();
    if (threadIdx.x == 0) atomicExch(&f[slot * 8], e);
}
__device__ __forceinline__ void flags_wait(unsigned* f, int n, unsigned e) {
    if ((int)threadIdx.x < n)
        while (__ldcg(&f[threadIdx.x * 8]) < e) __nanosleep(32);
    __syncthreads();
    __threadfence();
}
__device__ __forceinline__ void flag_wait_one(unsigned* f, int slot, unsigned e) {
    if (threadIdx.x == 0)
        while (__ldcg(&f[slot * 8]) < e) __nanosleep(32);
    __syncthreads();
    __threadfence();
}

// 4-rowtile warp GEMM, single B source: per kstep 8 A-uint4 + 8 B-uint2 + 48 MMA.
__device__ __forceinline__ void warp_gemm4(
    const uint32_t* __restrict__ Wt, int nk, int rt0, int k0, int kn,
    const uint32_t* __restrict__ x, float acc[4][4][4], int lane)
{
    const uint4* A[4];
    #pragma unroll
    for (int r = 0; r < 4; r++)
        A[r] = (const uint4*)Wt + ((size_t)(rt0 + r) * nk + k0) * 64 + lane;
    #pragma unroll 2
    for (int s = 0; s < kn; s++) {
        int ks = k0 + s;
        const uint2* xb = (const uint2*)(x + (size_t)(ks & 63) * 512);
        uint2 bh[4], bl[4];
        #pragma unroll
        for (int nt = 0; nt < 4; nt++) {
            bh[nt] = __ldcg(&xb[nt * 32 + lane]);
            bl[nt] = __ldcg(&xb[128 + nt * 32 + lane]);
        }
        #pragma unroll
        for (int r = 0; r < 4; r++) {
            uint4 ah = __ldg(A[r]);
            uint4 al = __ldg(A[r] + 32);
            A[r] += 64;
            #pragma unroll
            for (int nt = 0; nt < 4; nt++) {
                mma_bf16(acc[r][nt], (const uint32_t*)&ah, bh[nt].x, bh[nt].y);
                mma_bf16(acc[r][nt], (const uint32_t*)&ah, bl[nt].x, bl[nt].y);
                mma_bf16(acc[r][nt], (const uint32_t*)&al, bh[nt].x, bh[nt].y);
            }
        }
    }
}

// 2-rowtile variant (q / wo)
__device__ __forceinline__ void warp_gemm2s(
    const uint32_t* __restrict__ Wt, int nk, int rt0, int k0, int kn,
    const uint32_t* __restrict__ x, float acc[2][4][4], int lane)
{
    const uint4* A0 = (const uint4*)Wt + ((size_t)rt0 * nk + k0) * 64 + lane;
    const uint4* A1 = (const uint4*)Wt + ((size_t)(rt0 + 1) * nk + k0) * 64 + lane;
    #pragma unroll 2
    for (int s = 0; s < kn; s++) {
        int ks = k0 + s;
        const uint2* xb = (const uint2*)(x + (size_t)(ks & 63) * 512);
        uint2 bh[4], bl[4];
        #pragma unroll
        for (int nt = 0; nt < 4; nt++) {
            bh[nt] = __ldcg(&xb[nt * 32 + lane]);
            bl[nt] = __ldcg(&xb[128 + nt * 32 + lane]);
        }
        uint4 ah0 = __ldg(A0), al0 = __ldg(A0 + 32);
        uint4 ah1 = __ldg(A1), al1 = __ldg(A1 + 32);
        A0 += 64; A1 += 64;
        #pragma unroll
        for (int nt = 0; nt < 4; nt++) {
            mma_bf16(acc[0][nt], (const uint32_t*)&ah0, bh[nt].x, bh[nt].y);
            mma_bf16(acc[0][nt], (const uint32_t*)&ah0, bl[nt].x, bl[nt].y);
            mma_bf16(acc[0][nt], (const uint32_t*)&al0, bh[nt].x, bh[nt].y);
            mma_bf16(acc[1][nt], (const uint32_t*)&ah1, bh[nt].x, bh[nt].y);
            mma_bf16(acc[1][nt], (const uint32_t*)&ah1, bl[nt].x, bl[nt].y);
            mma_bf16(acc[1][nt], (const uint32_t*)&al1, bh[nt].x, bh[nt].y);
        }
    }
}

// red layout: red[(w*4 + rti)*512 + row16*32 + b]
__device__ __forceinline__ void acc_to_red(float* red, const float acc[4][4], int lane) {
    int gid = lane >> 2, tig = lane & 3;
    #pragma unroll
    for (int nt = 0; nt < 4; nt++) {
        int c = nt * 8 + tig * 2;
        red[gid * 32 + c]           = acc[nt][0];
        red[gid * 32 + c + 1]       = acc[nt][1];
        red[(gid + 8) * 32 + c]     = acc[nt][2];
        red[(gid + 8) * 32 + c + 1] = acc[nt][3];
    }
}

// LSTM cell: block covers hh [16*blk, 16*blk+16), gates = rowtile index (perm4).
__device__ __forceinline__ void cell_tail4(const float* __restrict__ red,
                                           const float* __restrict__ pp,
                                           const float* __restrict__ bih,
                                           const float* __restrict__ bhh,
                                           float* __restrict__ cT, uint32_t* __restrict__ hx,
                                           const float* __restrict__ ge,
                                           int blk, int tid)
{
    int bb = tid & 31;
    #pragma unroll
    for (int j = 0; j < 2; j++) {
        int hl = (tid >> 5) + j * 8;            // 0..15
        float gv[4];
        #pragma unroll
        for (int gt = 0; gt < 4; gt++) {
            int idx = hl * 32 + bb;
            float s = 0.f;
            #pragma unroll
            for (int w = 0; w < 8; w++) s += red[(w * 4 + gt) * 512 + idx];
            s += __ldcg(&pp[gt * 512 + idx]);
            if (ge) s += __ldg(&ge[(gt * 16 + hl) * 32 + bb]);
            gv[gt] = s;
        }
        int hh = blk * 16 + hl;
        float gi = gv[0] + bih[hh]            + bhh[hh];
        float gf = gv[1] + bih[1024 + hh]     + bhh[1024 + hh];
        float gg = gv[2] + bih[2048 + hh]     + bhh[2048 + hh];
        float go = gv[3] + bih[3072 + hh]     + bhh[3072 + hh];
        int e = hh * 32 + bb;
        float cn = sigm(gf) * cT[e] + sigm(gi) * tanhf(gg);
        cT[e] = cn;
        store_x((bf16*)hx, hh, bb, sigm(go) * tanhf(cn));
    }
}

// ---------------- persistent sequence kernel ----------------
__global__ void __launch_bounds__(256, 1)
k_seq(const float* __restrict__ ctx, const int* __restrict__ lens,
      const float* __restrict__ bih0, const float* __restrict__ bhh0,
      const float* __restrict__ bih1, const float* __restrict__ bhh1,
      float* __restrict__ outv, float* __restrict__ attnout)
{
    extern __shared__ float red[];     // 8*4*512 floats = 64KB
    __shared__ float sc[SS];
    int tid = threadIdx.x, w = tid >> 5, lane = tid & 31;
    int bid = blockIdx.x;
    bool lower = bid < 64;
    int pi = lower ? bid : bid - 64;   // pair index

    for (int t = 0; t < TT; t++) {
        unsigned ep = (unsigned)t + 1u;
        int p = t & 1;
        const uint32_t* h0o = g_h0x[p];
        uint32_t*       h0n = g_h0x[p ^ 1];
        const uint32_t* h1o = g_h1x[p];
        uint32_t*       h1n = g_h1x[p ^ 1];

        // ---- P1: pair K-split. lower = h0-half (no wait), upper = feed-half ----
        if (lower) {
            float acc[4][4][4] = {};
            warp_gemm4(g_w0, 192, bid * 4, 128 + w * 8, 8, h0o, acc, lane);
            #pragma unroll
            for (int r = 0; r < 4; r++) acc_to_red(&red[(w * 4 + r) * 512], acc[r], lane);
            __syncthreads();
            flag_wait_one(g_flagP1, bid, ep);
            cell_tail4(red, g_pp[bid], bih0, bhh0, g_c0T, h0n,
                       g_ge + (size_t)t * 4096 * 32 + (size_t)bid * 64 * 32, bid, tid);
        } else {
            flags_wait(g_flagF, 32, (unsigned)t);   // feed from step t-1
            float acc[4][4][4] = {};
            warp_gemm4(g_w0, 192, pi * 4, 64 + w * 8, 8, g_feedx, acc, lane);
            #pragma unroll
            for (int r = 0; r < 4; r++) acc_to_red(&red[(w * 4 + r) * 512], acc[r], lane);
            __syncthreads();
            #pragma unroll
            for (int j = 0; j < 8; j++) {
                int i = tid + j * 256;              // 2048 items
                int rti = i >> 9, idx = i & 511;
                float s = 0.f;
                #pragma unroll
                for (int ww = 0; ww < 8; ww++) s += red[(ww * 4 + rti) * 512 + idx];
                g_pp[pi][i] = s;
            }
            flag_set(g_flagP1, pi, ep);
        }
        flag_set(g_barA, bid, ep);
        flags_wait(g_barA, 128, ep);

        // ---- P2: lower = h0n-half (ks0-63), upper = h1o-half (ks64-127) ----
        if (lower) {
            float acc[4][4][4] = {};
            warp_gemm4(g_w1, 128, bid * 4, w * 8, 8, h0n, acc, lane);
            #pragma unroll
            for (int r = 0; r < 4; r++) acc_to_red(&red[(w * 4 + r) * 512], acc[r], lane);
            __syncthreads();
            flag_wait_one(g_flagP2, bid, ep);
            cell_tail4(red, g_pp[bid], bih1, bhh1, g_c1T, h1n, nullptr, bid, tid);
        } else {
            float acc[4][4][4] = {};
            warp_gemm4(g_w1, 128, pi * 4, 64 + w * 8, 8, h1o, acc, lane);
            #pragma unroll
            for (int r = 0; r < 4; r++) acc_to_red(&red[(w * 4 + r) * 512], acc[r], lane);
            __syncthreads();
            #pragma unroll
            for (int j = 0; j < 8; j++) {
                int i = tid + j * 256;
                int rti = i >> 9, idx = i & 511;
                float s = 0.f;
                #pragma unroll
                for (int ww = 0; ww < 8; ww++) s += red[(ww * 4 + rti) * 512 + idx];
                g_pp[pi][i] = s;
            }
            flag_set(g_flagP2, pi, ep);
        }
        flag_set(g_barB, bid, ep);
        flags_wait(g_barB, 128, ep);

        // ---- P3/P4/P5 ----
        if (bid < 32) {
            // q GEMM: 2 rowtiles, full K=64
            float acc[2][4][4] = {};
            warp_gemm2s(g_wq, 64, bid * 2, w * 8, 8, h1n, acc, lane);
            acc_to_red(&red[(w * 4 + 0) * 512], acc[0], lane);
            acc_to_red(&red[(w * 4 + 1) * 512], acc[1], lane);
            __syncthreads();
            #pragma unroll
            for (int j = 0; j < 4; j++) {
                int i = tid + j * 256;              // 1024 items
                int rti = i >> 9, idx = i & 511;
                float s = 0.f;
                #pragma unroll
                for (int ww = 0; ww < 8; ww++) s += red[(ww * 4 + rti) * 512 + idx];
                int row = bid * 32 + (i >> 5), bb = i & 31;
                g_qf[(size_t)bb * HH + row] = s;
            }
            flag_set(g_flagQ, bid, ep);
        } else if (bid < 64) {
            // attention, b = bid-32
            flags_wait(g_flagQ, 32, ep);
            int b = bid - 32;
            float* qs = red;                        // 1024 floats
            for (int i = tid; i < HH; i += 256)
                qs[i] = __ldcg(&g_qf[(size_t)b * HH + i]);
            __syncthreads();

            #pragma unroll
            for (int si = 0; si < 8; si++) {
                int s = w * 8 + si;
                const float* cr = ctx + ((size_t)s * BB + b) * HH;
                float sum = 0.f;
                for (int i = lane; i < HH; i += 32) sum = fmaf(qs[i], __ldg(&cr[i]), sum);
                #pragma unroll
                for (int o = 16; o > 0; o >>= 1) sum += __shfl_xor_sync(0xffffffffu, sum, o);
                if (lane == 0) sc[s] = sum;
            }
            __syncthreads();

            if (tid == 0) {
                int len = lens[b];
                len = len < 1 ? 1 : (len > SS ? SS : len);
                float m = sc[0];
                for (int s = 1; s < len; s++) m = fmaxf(m, sc[s]);
                float sum = 0.f;
                for (int s = 0; s < len; s++) { float e = expf(sc[s] - m); sc[s] = e; sum += e; }
                float inv = 1.f / sum;
                for (int s = 0; s < len; s++) sc[s] *= inv;
                for (int s = len; s < SS; s++) sc[s] = 0.f;
            }
            __syncthreads();

            if (tid < SS) attnout[((size_t)t * BB + b) * SS + tid] = sc[tid];

            #pragma unroll
            for (int j = 0; j < 4; j++) {
                int hh = tid + j * 256;
                float a = 0.f;
                for (int s = 0; s < SS; s++)
                    a = fmaf(sc[s], __ldg(&ctx[((size_t)s * BB + b) * HH + hh]), a);
                store_x((bf16*)g_cvx, hh, b, a);
            }
            flag_set(g_flagCV, b, ep);
        } else if (bid < 96) {
            // wo h1-half: rowtiles 2i, 2i+1; ks 64-127; runs free after barB
            int i = bid - 64;
            float acc[2][4][4] = {};
            warp_gemm2s(g_wo, 128, i * 2, 64 + w * 8, 8, h1n, acc, lane);
            acc_to_red(&red[(w * 4 + 0) * 512], acc[0], lane);
            acc_to_red(&red[(w * 4 + 1) * 512], acc[1], lane);
            __syncthreads();
            #pragma unroll
            for (int j = 0; j < 4; j++) {
                int i2 = tid + j * 256;
                int rti = i2 >> 9, idx = i2 & 511;
                float s = 0.f;
                #pragma unroll
                for (int ww = 0; ww < 8; ww++) s += red[(ww * 4 + rti) * 512 + idx];
                g_pp[32 + i][i2] = s;
            }
            flag_set(g_flagPO, i, ep);
        } else {
            // wo cvec-half + epilogue
            int i = bid - 96;
            flags_wait(g_flagCV, 32, ep);
            float acc[2][4][4] = {};
            warp_gemm2s(g_wo, 128, i * 2, w * 8, 8, g_cvx, acc, lane);
            acc_to_red(&red[(w * 4 + 0) * 512], acc[0], lane);
            acc_to_red(&red[(w * 4 + 1) * 512], acc[1], lane);
            __syncthreads();
            flag_wait_one(g_flagPO, i, ep);
            #pragma unroll
            for (int j = 0; j < 4; j++) {
                int i2 = tid + j * 256;
                int rti = i2 >> 9, idx = i2 & 511;
                float v = 0.f;
                #pragma unroll
                for (int ww = 0; ww < 8; ww++) v += red[(ww * 4 + rti) * 512 + idx];
                v += __ldcg(&g_pp[32 + i][i2]);
                v = tanhf(v);
                int hh = i * 32 + (i2 >> 5), bb = i2 & 31;
                outv[((size_t)t * BB + bb) * HH + hh] = v;
                store_x((bf16*)g_feedx, hh, bb, v);
            }
            flag_set(g_flagF, i, ep);
        }
    }
}

// ---------------- prologue: gates0 emb contribution for ALL t ----------------
__global__ void __launch_bounds__(256, 1)
k_embgemm() {
    __shared__ uint32_t stage[4][512];
    int tid = threadIdx.x, w = tid >> 5, lane = tid & 31;
    int Mb = blockIdx.x, tg = blockIdx.y;
    int rt = Mb * 8 + w;

    float acc[4][4][4] = {};
    const uint4* Ap = (const uint4*)g_w0 + ((size_t)rt * 192) * 64 + lane;

    for (int ks = 0; ks < 64; ks++) {
        __syncthreads();
        #pragma unroll
        for (int j = 0; j < 8; j++) {
            int u = tid + j * 256;
            stage[u >> 9][u & 511] =
                __ldg(&g_embx[(size_t)(tg * 4 + (u >> 9)) * 32768 + (size_t)ks * 512 + (u & 511)]);
        }
        __syncthreads();
        uint4 ah = __ldg(Ap), al = __ldg(Ap + 32);
        Ap += 64;
        #pragma unroll
        for (int tt = 0; tt < 4; tt++) {
            const uint2* xb = (const uint2*)stage[tt];
            #pragma unroll
            for (int nt = 0; nt < 4; nt++) {
                uint2 bh = xb[nt * 32 + lane];
                uint2 bl = xb[128 + nt * 32 + lane];
                mma_bf16(acc[tt][nt], (const uint32_t*)&ah, bh.x, bh.y);
                mma_bf16(acc[tt][nt], (const uint32_t*)&ah, bl.x, bl.y);
                mma_bf16(acc[tt][nt], (const uint32_t*)&al, bh.x, bh.y);
            }
        }
    }

    int gid = lane >> 2, tig = lane & 3;
    #pragma unroll
    for (int tt = 0; tt < 4; tt++) {
        float* gp = g_ge + ((size_t)(tg * 4 + tt) * 4096) * 32;
        #pragma unroll
        for (int nt = 0; nt < 4; nt++) {
            int row0 = rt * 16 + gid, col = nt * 8 + tig * 2;
            *(float2*)&gp[(size_t)row0 * 32 + col] = make_float2(acc[tt][nt][0], acc[tt][nt][1]);
            *(float2*)&gp[(size_t)(row0 + 8) * 32 + col] = make_float2(acc[tt][nt][2], acc[tt][nt][3]);
        }
    }
}

// ---------------- weight conversion ----------------
// perm4: rowtile rt, frag row i -> pib=(rt&3)*16+i; gate=pib>>4; hho=pib&15;
// logical row = gate*1024 + (rt>>2)*16 + hho.
__device__ __forceinline__ void wconv_one(const float* __restrict__ W, int ldw,
                                          uint32_t* __restrict__ dst, int nkTot, int ksBase,
                                          int gatePerm, int rt, int ks) {
    int lane = threadIdx.x;
    int gid = lane >> 2, tig = lane & 3;
    uint32_t hi[4], lo[4];
    #pragma unroll
    for (int r = 0; r < 4; r++) {
        int i = gid + (r & 1) * 8;
        int row;
        if (gatePerm) {
            int pib = (rt & 3) * 16 + i;
            int gate = pib >> 4, hho = pib & 15;
            row = gate * 1024 + (rt >> 2) * 16 + hho;
        } else {
            row = rt * 16 + i;
        }
        int kk = ks * 16 + (r >> 1) * 8 + tig * 2;
        float w0 = __ldg(&W[(size_t)row * ldw + kk]);
        float w1 = __ldg(&W[(size_t)row * ldw + kk + 1]);
        bf16 h0 = __float2bfloat16(w0), h1 = __float2bfloat16(w1);
        bf16 l0 = __float2bfloat16(w0 - __bfloat162float(h0));
        bf16 l1 = __float2bfloat16(w1 - __bfloat162float(h1));
        hi[r] = ((uint32_t)__bfloat16_as_ushort(h1) << 16) | __bfloat16_as_ushort(h0);
        lo[r] = ((uint32_t)__bfloat16_as_ushort(l1) << 16) | __bfloat16_as_ushort(l0);
    }
    size_t bi = (((size_t)rt * nkTot + ksBase + ks) * 2) * 128 + lane * 4;
    #pragma unroll
    for (int r = 0; r < 4; r++) {
        dst[bi + r] = hi[r];
        dst[bi + 128 + r] = lo[r];
    }
}

__global__ void k_wconvAll(const float* ih0, const float* hh0, const float* ih1,
                           const float* hh1, const float* win, const float* wout) {
    int rt = blockIdx.x, ks = blockIdx.y, z = blockIdx.z;
    switch (z) {
        case 0: wconv_one(ih0, 2048, g_w0, 192, 0, 1, rt, ks); break;                 // ks<128
        case 1: if (ks < 64) wconv_one(hh0, 1024, g_w0, 192, 128, 1, rt, ks); break;
        case 2: if (ks < 64) wconv_one(ih1, 1024, g_w1, 128, 0,   1, rt, ks); break;
        case 3: if (ks < 64) wconv_one(hh1, 1024, g_w1, 128, 64,  1, rt, ks); break;
        case 4: if (rt < 64 && ks < 64) wconv_one(win,  1024, g_wq, 64,  0, 0, rt, ks); break;
        default: if (rt < 64) wconv_one(wout, 2048, g_wo, 128, 0, 0, rt, ks); break;  // ks<128
    }
}

// ---------------- embx + init merged ----------------
__global__ void k_embx_init(const int* __restrict__ ids, const float* __restrict__ emb,
                            const float* __restrict__ h0, const float* __restrict__ c0) {
    int tid = threadIdx.x;
    if (blockIdx.x < 64) {
        int t = blockIdx.x;
        int b = tid & 31;
        int id = ids[t * BB + b];
        bf16* dstx = (bf16*)(g_embx + (size_t)t * 32768);
        const float* src = emb + (size_t)id * HH;
        for (int hh = tid >> 5; hh < HH; hh += 8)
            store_x(dstx, hh, b, __ldg(&src[hh]));
    } else {
        int idx = (blockIdx.x - 64) * 256 + tid;
        if (idx < 128 * 8) { g_barA[idx] = 0u; g_barB[idx] = 0u; }
        if (idx < 64 * 8)  { g_flagP1[idx] = 0u; g_flagP2[idx] = 0u; }
        if (idx < 32 * 8)  { g_flagPO[idx] = 0u; g_flagQ[idx] = 0u; g_flagCV[idx] = 0u; g_flagF[idx] = 0u; }
        if (idx >= HH * BB) return;
        int hh = idx >> 5, b = idx & 31;
        g_c0T[idx] = c0[(size_t)(0 * BB + b) * HH + hh];
        g_c1T[idx] = c0[(size_t)(1 * BB + b) * HH + hh];
        store_x((bf16*)g_h0x[0], hh, b, h0[(size_t)(0 * BB + b) * HH + hh]);
        store_x((bf16*)g_h1x[0], hh, b, h0[(size_t)(1 * BB + b) * HH + hh]);
        store_x((bf16*)g_feedx, hh, b, 0.f);
    }
}

// ---------------- launcher (graph-capturable: kernel launches only) ----------------
extern "C" void kernel_launch(void* const* d_in, const int* in_sizes, int n_in,
                              void* d_out, int out_size) {
    const int*   ids   = (const int*)  d_in[0];
    const float* ctx   = (const float*)d_in[1];
    const int*   lens  = (const int*)  d_in[2];
    const float* h0    = (const float*)d_in[3];
    const float* c0    = (const float*)d_in[4];
    const float* emb   = (const float*)d_in[5];
    const float* W_ih0 = (const float*)d_in[6];
    const float* W_hh0 = (const float*)d_in[7];
    const float* b_ih0 = (const float*)d_in[8];
    const float* b_hh0 = (const float*)d_in[9];
    const float* W_ih1 = (const float*)d_in[10];
    const float* W_hh1 = (const float*)d_in[11];
    const float* b_ih1 = (const float*)d_in[12];
    const float* b_hh1 = (const float*)d_in[13];
    const float* W_in  = (const float*)d_in[14];
    const float* W_out = (const float*)d_in[15];

    float* outv = (float*)d_out;                      // outputs [T,B,H]
    float* attn = outv + (size_t)TT * BB * HH;        // attns   [T,B,S]

    static int smem_set = 0;
    if (!smem_set) {
        cudaFuncSetAttribute(k_seq, cudaFuncAttributeMaxDynamicSharedMemorySize, 66000);
        smem_set = 1;
    }

    // 3 setup launches, then k_seq (our launch #4)
    k_wconvAll<<<dim3(256, 128, 6), 32>>>(W_ih0, W_hh0, W_ih1, W_hh1, W_in, W_out);
    k_embx_init<<<192, 256>>>(ids, emb, h0, c0);
    k_embgemm<<<dim3(32, 16), 256>>>();

    k_seq<<<NBLK, 256, 65536>>>(ctx, lens, b_ih0, b_hh0, b_ih1, b_hh1, outv, attn);
}

// round 16
// speedup vs baseline: 1.0677x; 1.0677x over previous
#include <cuda_runtime.h>
#include <cuda_bf16.h>
#include <math.h>
#include <stdint.h>

#define TT 64
#define BB 32
#define SS 64
#define HH 1024
#define NBLK 128

typedef __nv_bfloat16 bf16;

// ---------------- static device scratch (no allocations) ----------------
// Weight fragments (uint32): [rowtile16][kstep][sel hi/lo][lane(32)][reg(4)]
// gates use gate-permuted rows: rt pair per block, pib=(rt&1)*16+i, gate=pib>>3.
__device__ uint32_t g_w0[(size_t)256 * 192 * 2 * 128];  // ks 0-63 ih0-emb, 64-127 ih0-feed, 128-191 hh0
__device__ uint32_t g_w1[(size_t)256 * 128 * 2 * 128];  // ks 0-63 ih1(h0), 64-127 hh1(h1)
__device__ uint32_t g_wq[(size_t)64 * 64 * 2 * 128];    // W_in^T (for cq prologue)
__device__ uint32_t g_wo[(size_t)64 * 128 * 2 * 128];   // W_out: ks 0-63 cvec-half, 64-127 h1-half

// Activation B-fragments: per 1024-k vector: [kstep(64)][sel(2)][ntile(4)][lane(32)][reg(2)]
__device__ uint32_t g_embx[(size_t)TT * 32768];
__device__ uint32_t g_ctxx[(size_t)SS * 32768];  // ctx[s] fragments (prologue only)
__device__ uint32_t g_h0x[2][32768];             // double-buffered
__device__ uint32_t g_h1x[2][32768];
__device__ uint32_t g_feedx[32768];

__device__ float g_ge[(size_t)TT * 4096 * 32];   // W_ih0_emb @ emb_t  (fragment-row order)
__device__ float g_pctx[(size_t)SS * BB * HH];   // W_out_cvec @ ctx   [s][b][hh]
__device__ float g_cq[(size_t)SS * BB * HH];     // W_in^T @ ctx       [s][b][hh]
__device__ float g_c0T[HH * BB];                 // [hh][b]
__device__ float g_c1T[HH * BB];
__device__ float g_h1f[BB * HH];                 // fp32 h1, [b][hh]
__device__ float g_po[HH * BB];                  // W_out_h1 @ h1, [row][b]

// epoch flags (32B padded, monotonic)
__device__ unsigned g_barA[128 * 8];
__device__ unsigned g_barB[128 * 8];
__device__ unsigned g_flagW[32 * 8];
__device__ unsigned g_flagF[32 * 8];

// ---------------- helpers ----------------
__device__ __forceinline__ float sigm(float x) { return 1.f / (1.f + expf(-x)); }

__device__ __forceinline__ void store_x(bf16* base, int hh, int b, float v) {
    int kstep = hh >> 4, kk = hh & 15;
    int ntile = b >> 3, gid = b & 7;
    int reg = kk >> 3, krem = kk & 7, tig = krem >> 1, half = krem & 1;
    int lane = gid * 4 + tig;
    bf16 hi = __float2bfloat16(v);
    bf16 lo = __float2bfloat16(v - __bfloat162float(hi));
    size_t i0 = ((((size_t)kstep * 2 + 0) * 4 + ntile) * 64 + lane * 2 + reg) * 2 + half;
    size_t i1 = ((((size_t)kstep * 2 + 1) * 4 + ntile) * 64 + lane * 2 + reg) * 2 + half;
    base[i0] = hi;
    base[i1] = lo;
}

__device__ __forceinline__ void mma_bf16(float* d, const uint32_t* a, uint32_t b0, uint32_t b1) {
    asm volatile(
        "mma.sync.aligned.m16n8k16.row.col.f32.bf16.bf16.f32 "
        "{%0,%1,%2,%3}, {%4,%5,%6,%7}, {%8,%9}, {%0,%1,%2,%3};"
        : "+f"(d[0]), "+f"(d[1]), "+f"(d[2]), "+f"(d[3])
        : "r"(a[0]), "r"(a[1]), "r"(a[2]), "r"(a[3]), "r"(b0), "r"(b1));
}

__device__ __forceinline__ void flag_set(unsigned* f, int slot, unsigned e) {
    __syncthreads();
    __threadfence();
    if (threadIdx.x == 0) atomicExch(&f[slot * 8], e);
}
__device__ __forceinline__ void flags_wait(unsigned* f, int n, unsigned e) {
    if ((int)threadIdx.x < n)
        while (__ldcg(&f[threadIdx.x * 8]) < e) __nanosleep(32);
    __syncthreads();
    __threadfence();
}
// warp-scope: each lane polls one of the 32 feed flags
__device__ __forceinline__ void warp_wait_feed(unsigned e, int lane) {
    while (__ldcg(&g_flagF[lane * 8]) < e) __nanosleep(32);
    __syncwarp();
    __threadfence();
}

// 2-rowtile warp GEMM: B loaded once per kstep, used for rt0 and rt0+1.
__device__ __forceinline__ void warp_gemm2(
    const uint32_t* __restrict__ Wt, int nk, int rt0, int k0, int kn, int split,
    const uint32_t* __restrict__ xlo, const uint32_t* __restrict__ xhi,
    float acc[2][4][4], int lane)
{
    const uint4* A0 = (const uint4*)Wt + ((size_t)rt0 * nk + k0) * 64 + lane;
    const uint4* A1 = (const uint4*)Wt + ((size_t)(rt0 + 1) * nk + k0) * 64 + lane;
    #pragma unroll 4
    for (int s = 0; s < kn; s++) {
        int ks = k0 + s;
        const uint32_t* xs = (ks < split) ? xlo : xhi;
        const uint2* xb = (const uint2*)(xs + (size_t)(ks & 63) * 512);
        uint2 bh[4], bl[4];
        #pragma unroll
        for (int nt = 0; nt < 4; nt++) {
            bh[nt] = __ldcg(&xb[nt * 32 + lane]);
            bl[nt] = __ldcg(&xb[128 + nt * 32 + lane]);
        }
        uint4 ah0 = __ldg(A0), al0 = __ldg(A0 + 32);
        uint4 ah1 = __ldg(A1), al1 = __ldg(A1 + 32);
        A0 += 64; A1 += 64;
        #pragma unroll
        for (int nt = 0; nt < 4; nt++) {
            mma_bf16(acc[0][nt], (const uint32_t*)&ah0, bh[nt].x, bh[nt].y);
            mma_bf16(acc[0][nt], (const uint32_t*)&ah0, bl[nt].x, bl[nt].y);
            mma_bf16(acc[0][nt], (const uint32_t*)&al0, bh[nt].x, bh[nt].y);
            mma_bf16(acc[1][nt], (const uint32_t*)&ah1, bh[nt].x, bh[nt].y);
            mma_bf16(acc[1][nt], (const uint32_t*)&ah1, bl[nt].x, bl[nt].y);
            mma_bf16(acc[1][nt], (const uint32_t*)&al1, bh[nt].x, bh[nt].y);
        }
    }
}

__device__ __forceinline__ void acc_to_red(float* red, const float acc[4][4], int lane) {
    int gid = lane >> 2, tig = lane & 3;
    #pragma unroll
    for (int nt = 0; nt < 4; nt++) {
        int c = nt * 8 + tig * 2;
        red[gid * 32 + c]           = acc[nt][0];
        red[gid * 32 + c + 1]       = acc[nt][1];
        red[(gid + 8) * 32 + c]     = acc[nt][2];
        red[(gid + 8) * 32 + c + 1] = acc[nt][3];
    }
}

// LSTM cell tail: block covers hh [8*bid, 8*bid+8); h1f!=nullptr also stores fp32 h.
__device__ __forceinline__ void cell_tail(const float (*red)[2][512],
                                          const float* __restrict__ bih,
                                          const float* __restrict__ bhh,
                                          float* __restrict__ cT, uint32_t* __restrict__ hx,
                                          const float* __restrict__ ge,
                                          float* __restrict__ h1f,
                                          int bid, int tid)
{
    int hl = tid >> 5, bb = tid & 31;
    float gv[4];
    #pragma unroll
    for (int gt = 0; gt < 4; gt++) {
        int pib = gt * 8 + hl;
        int par = pib >> 4;
        int idx = (pib & 15) * 32 + bb;
        float s = 0.f;
        #pragma unroll
        for (int kc = 0; kc < 8; kc++) s += red[kc][par][idx];
        if (ge) s += __ldg(&ge[(size_t)(bid * 32 + pib) * 32 + bb]);
        gv[gt] = s;
    }
    int hh = bid * 8 + hl;
    float gi = gv[0] + bih[hh]            + bhh[hh];
    float gf = gv[1] + bih[1024 + hh]     + bhh[1024 + hh];
    float gg = gv[2] + bih[2048 + hh]     + bhh[2048 + hh];
    float go = gv[3] + bih[3072 + hh]     + bhh[3072 + hh];
    int e = hh * 32 + bb;
    float cn = sigm(gf) * cT[e] + sigm(gi) * tanhf(gg);
    cT[e] = cn;
    float h = sigm(go) * tanhf(cn);
    if (h1f) h1f[(size_t)bb * HH + hh] = h;
    store_x((bf16*)hx, hh, bb, h);
}

// ---------------- persistent sequence kernel ----------------
__global__ void __launch_bounds__(256, 1)
k_seq(const float* __restrict__ ctx, const int* __restrict__ lens,
      const float* __restrict__ bih0, const float* __restrict__ bhh0,
      const float* __restrict__ bih1, const float* __restrict__ bhh1,
      float* __restrict__ outv, float* __restrict__ attnout)
{
    __shared__ float red[8][2][512];   // 32KB (reused as qs in attention)
    __shared__ float sc[SS];
    int tid = threadIdx.x, w = tid >> 5, lane = tid & 31;
    int bid = blockIdx.x;

    for (int t = 0; t < TT; t++) {
        unsigned ep = (unsigned)t + 1u;
        int p = t & 1;
        const uint32_t* h0o = g_h0x[p];
        uint32_t*       h0n = g_h0x[p ^ 1];
        const uint32_t* h1o = g_h1x[p];
        uint32_t*       h1n = g_h1x[p ^ 1];

        // ---- P1: gates0. h0-half first (no wait), then feed-half after flagF(t-1) ----
        {
            float acc[2][4][4] = {};
            warp_gemm2(g_w0, 192, bid * 2, 128 + w * 8, 8, 128, g_feedx, h0o, acc, lane);
            warp_wait_feed((unsigned)t, lane);
            warp_gemm2(g_w0, 192, bid * 2, 64 + w * 8, 8, 128, g_feedx, h0o, acc, lane);
            acc_to_red(red[w][0], acc[0], lane);
            acc_to_red(red[w][1], acc[1], lane);
            __syncthreads();
            cell_tail(red, bih0, bhh0, g_c0T, h0n,
                      g_ge + (size_t)t * 4096 * 32, nullptr, bid, tid);
        }
        flag_set(g_barA, bid, ep);
        flags_wait(g_barA, 128, ep);

        // ---- P2: gates1 (h0n ks0-63, h1o ks64-127) + cell1 (also writes fp32 h1) ----
        {
            float acc[2][4][4] = {};
            warp_gemm2(g_w1, 128, bid * 2, w * 16, 16, 64, h0n, h1o, acc, lane);
            acc_to_red(red[w][0], acc[0], lane);
            acc_to_red(red[w][1], acc[1], lane);
            __syncthreads();
            cell_tail(red, bih1, bhh1, g_c1T, h1n, nullptr, g_h1f, bid, tid);
        }
        flag_set(g_barB, bid, ep);
        flags_wait(g_barB, 128, ep);

        // ---- P3 (parallel): blocks 0-31 attention+output; 32-63 W_out h1-half GEMM ----
        if (bid < 32) {
            int b = bid;
            float* qs = &red[0][0][0];            // 1024 floats
            for (int i = tid; i < HH; i += 256)
                qs[i] = __ldcg(&g_h1f[(size_t)b * HH + i]);
            __syncthreads();

            // scores[s] = h1 . cq[s,b,:]
            #pragma unroll
            for (int si = 0; si < 8; si++) {
                int s = w * 8 + si;
                const float* cr = g_cq + ((size_t)s * BB + b) * HH;
                float sum = 0.f;
                for (int i = lane; i < HH; i += 32) sum = fmaf(qs[i], __ldg(&cr[i]), sum);
                #pragma unroll
                for (int o = 16; o > 0; o >>= 1) sum += __shfl_xor_sync(0xffffffffu, sum, o);
                if (lane == 0) sc[s] = sum;
            }
            __syncthreads();

            if (tid == 0) {
                int len = lens[b];
                len = len < 1 ? 1 : (len > SS ? SS : len);
                float m = sc[0];
                for (int s = 1; s < len; s++) m = fmaxf(m, sc[s]);
                float sum = 0.f;
                for (int s = 0; s < len; s++) { float e = expf(sc[s] - m); sc[s] = e; sum += e; }
                float inv = 1.f / sum;
                for (int s = 0; s < len; s++) sc[s] *= inv;
                for (int s = len; s < SS; s++) sc[s] = 0.f;
            }
            __syncthreads();

            if (tid < SS) attnout[((size_t)t * BB + b) * SS + tid] = sc[tid];

            // cvec-half of pre-output directly: a[hh] = sum_s attn[s] * pctx[s,b,hh]
            float a[4] = {0.f, 0.f, 0.f, 0.f};
            for (int s = 0; s < SS; s++) {
                float as = sc[s];
                const float* pr = g_pctx + ((size_t)s * BB + b) * HH;
                #pragma unroll
                for (int j = 0; j < 4; j++)
                    a[j] = fmaf(as, __ldg(&pr[tid + j * 256]), a[j]);
            }

            flags_wait(g_flagW, 32, ep);          // h1-half of pre-output ready
            #pragma unroll
            for (int j = 0; j < 4; j++) {
                int hh = tid + j * 256;
                float v = tanhf(a[j] + __ldcg(&g_po[(size_t)hh * 32 + b]));
                outv[((size_t)t * BB + b) * HH + hh] = v;
                store_x((bf16*)g_feedx, hh, b, v);
            }
            flag_set(g_flagF, b, ep);
        } else if (bid < 64) {
            // W_out h1-half: rowtiles 2i, 2i+1; ks 64-127
            int i = bid - 32;
            float acc[2][4][4] = {};
            warp_gemm2(g_wo, 128, i * 2, 64 + w * 8, 8, 64, h1n, h1n, acc, lane);
            acc_to_red(red[w][0], acc[0], lane);
            acc_to_red(red[w][1], acc[1], lane);
            __syncthreads();
            #pragma unroll
            for (int j = 0; j < 4; j++) {
                int i2 = tid + j * 256;           // 1024 items
                int rti = i2 >> 9, idx = i2 & 511;
                float s = 0.f;
                #pragma unroll
                for (int ww = 0; ww < 8; ww++) s += red[ww][rti][idx];
                int row = i * 32 + rti * 16 + (idx >> 5), bb = idx & 31;
                g_po[(size_t)row * 32 + bb] = s;
            }
            flag_set(g_flagW, i, ep);
        }
        // blocks 64-127: idle in P3, race ahead into next step's P1 h0-half
    }
}

// ---------------- prologue GEMMs: emb (z=0) and pctx/cq (z=1) ----------------
__global__ void __launch_bounds__(256, 1)
k_progemm() {
    __shared__ uint32_t stage[4][512];
    int tid = threadIdx.x, w = tid >> 5, lane = tid & 31;
    int Mb = blockIdx.x, tg = blockIdx.y, z = blockIdx.z;

    const uint32_t* bsrc;
    const uint4* Ap;
    int rtLocal;
    if (z == 0) {
        bsrc = g_embx;
        rtLocal = Mb * 8 + w;                       // 0..255
        Ap = (const uint4*)g_w0 + ((size_t)rtLocal * 192) * 64 + lane;
    } else {
        if (Mb >= 16) return;
        bsrc = g_ctxx;
        if (Mb < 8) {
            rtLocal = Mb * 8 + w;                   // 0..63
            Ap = (const uint4*)g_wo + ((size_t)rtLocal * 128) * 64 + lane;
        } else {
            rtLocal = (Mb - 8) * 8 + w;
            Ap = (const uint4*)g_wq + ((size_t)rtLocal * 64) * 64 + lane;
        }
    }

    float acc[4][4][4] = {};
    for (int ks = 0; ks < 64; ks++) {
        __syncthreads();
        #pragma unroll
        for (int j = 0; j < 8; j++) {
            int u = tid + j * 256;
            stage[u >> 9][u & 511] =
                __ldg(&bsrc[(size_t)(tg * 4 + (u >> 9)) * 32768 + (size_t)ks * 512 + (u & 511)]);
        }
        __syncthreads();
        uint4 ah = __ldg(Ap), al = __ldg(Ap + 32);
        Ap += 64;
        #pragma unroll
        for (int tt = 0; tt < 4; tt++) {
            const uint2* xb = (const uint2*)stage[tt];
            #pragma unroll
            for (int nt = 0; nt < 4; nt++) {
                uint2 bh = xb[nt * 32 + lane];
                uint2 bl = xb[128 + nt * 32 + lane];
                mma_bf16(acc[tt][nt], (const uint32_t*)&ah, bh.x, bh.y);
                mma_bf16(acc[tt][nt], (const uint32_t*)&ah, bl.x, bl.y);
                mma_bf16(acc[tt][nt], (const uint32_t*)&al, bh.x, bh.y);
            }
        }
    }

    int gid = lane >> 2, tig = lane & 3;
    if (z == 0) {
        #pragma unroll
        for (int tt = 0; tt < 4; tt++) {
            float* gp = g_ge + ((size_t)(tg * 4 + tt) * 4096) * 32;
            #pragma unroll
            for (int nt = 0; nt < 4; nt++) {
                int row0 = rtLocal * 16 + gid, col = nt * 8 + tig * 2;
                *(float2*)&gp[(size_t)row0 * 32 + col] = make_float2(acc[tt][nt][0], acc[tt][nt][1]);
                *(float2*)&gp[(size_t)(row0 + 8) * 32 + col] = make_float2(acc[tt][nt][2], acc[tt][nt][3]);
            }
        }
    } else {
        float* dst = (Mb < 8) ? g_pctx : g_cq;
        #pragma unroll
        for (int tt = 0; tt < 4; tt++) {
            int s = tg * 4 + tt;
            #pragma unroll
            for (int nt = 0; nt < 4; nt++) {
                int row0 = rtLocal * 16 + gid, col = nt * 8 + tig * 2;
                dst[((size_t)s * BB + col)     * HH + row0]     = acc[tt][nt][0];
                dst[((size_t)s * BB + col + 1) * HH + row0]     = acc[tt][nt][1];
                dst[((size_t)s * BB + col)     * HH + row0 + 8] = acc[tt][nt][2];
                dst[((size_t)s * BB + col + 1) * HH + row0 + 8] = acc[tt][nt][3];
            }
        }
    }
}

// ---------------- weight conversion ----------------
__device__ __forceinline__ void wconv_one(const float* __restrict__ W, int ldw,
                                          uint32_t* __restrict__ dst, int nkTot, int ksBase,
                                          int gatePerm, int transp, int rt, int ks) {
    int lane = threadIdx.x;
    int gid = lane >> 2, tig = lane & 3;
    uint32_t hi[4], lo[4];
    #pragma unroll
    for (int r = 0; r < 4; r++) {
        int i = gid + (r & 1) * 8;
        int row;
        if (gatePerm) {
            int pib = (rt & 1) * 16 + i;
            int gate = pib >> 3, hho = pib & 7;
            row = gate * 1024 + (rt >> 1) * 8 + hho;
        } else {
            row = rt * 16 + i;
        }
        int kk = ks * 16 + (r >> 1) * 8 + tig * 2;
        float w0, w1;
        if (transp) {
            w0 = __ldg(&W[(size_t)kk * ldw + row]);
            w1 = __ldg(&W[(size_t)(kk + 1) * ldw + row]);
        } else {
            w0 = __ldg(&W[(size_t)row * ldw + kk]);
            w1 = __ldg(&W[(size_t)row * ldw + kk + 1]);
        }
        bf16 h0 = __float2bfloat16(w0), h1 = __float2bfloat16(w1);
        bf16 l0 = __float2bfloat16(w0 - __bfloat162float(h0));
        bf16 l1 = __float2bfloat16(w1 - __bfloat162float(h1));
        hi[r] = ((uint32_t)__bfloat16_as_ushort(h1) << 16) | __bfloat16_as_ushort(h0);
        lo[r] = ((uint32_t)__bfloat16_as_ushort(l1) << 16) | __bfloat16_as_ushort(l0);
    }
    size_t bi = (((size_t)rt * nkTot + ksBase + ks) * 2) * 128 + lane * 4;
    #pragma unroll
    for (int r = 0; r < 4; r++) {
        dst[bi + r] = hi[r];
        dst[bi + 128 + r] = lo[r];
    }
}

__global__ void k_wconvAll(const float* ih0, const float* hh0, const float* ih1,
                           const float* hh1, const float* win, const float* wout) {
    int rt = blockIdx.x, ks = blockIdx.y, z = blockIdx.z;
    switch (z) {
        case 0: wconv_one(ih0, 2048, g_w0, 192, 0, 1, 0, rt, ks); break;                 // ks<128
        case 1: if (ks < 64) wconv_one(hh0, 1024, g_w0, 192, 128, 1, 0, rt, ks); break;
        case 2: if (ks < 64) wconv_one(ih1, 1024, g_w1, 128, 0,   1, 0, rt, ks); break;
        case 3: if (ks < 64) wconv_one(hh1, 1024, g_w1, 128, 64,  1, 0, rt, ks); break;
        case 4: if (rt < 64 && ks < 64) wconv_one(win, 1024, g_wq, 64, 0, 0, 1, rt, ks); break;  // W_in^T
        default: if (rt < 64) wconv_one(wout, 2048, g_wo, 128, 0, 0, 0, rt, ks); break;  // ks<128
    }
}

// ---------------- embx + ctxx + init ----------------
__global__ void k_embx_init(const int* __restrict__ ids, const float* __restrict__ emb,
                            const float* __restrict__ ctx,
                            const float* __restrict__ h0, const float* __restrict__ c0) {
    int tid = threadIdx.x;
    int bid = blockIdx.x;
    if (bid < 64) {
        int t = bid;
        int b = tid & 31;
        int id = ids[t * BB + b];
        bf16* dstx = (bf16*)(g_embx + (size_t)t * 32768);
        const float* src = emb + (size_t)id * HH;
        for (int hh = tid >> 5; hh < HH; hh += 8)
            store_x(dstx, hh, b, __ldg(&src[hh]));
    } else if (bid < 128) {
        int s = bid - 64;
        int b = tid & 31;
        bf16* dstx = (bf16*)(g_ctxx + (size_t)s * 32768);
        const float* src = ctx + ((size_t)s * BB + b) * HH;
        for (int hh = tid >> 5; hh < HH; hh += 8)
            store_x(dstx, hh, b, __ldg(&src[hh]));
    } else {
        int idx = (bid - 128) * 256 + tid;
        if (idx < 128 * 8) { g_barA[idx] = 0u; g_barB[idx] = 0u; }
        if (idx < 32 * 8)  { g_flagW[idx] = 0u; g_flagF[idx] = 0u; }
        if (idx >= HH * BB) return;
        int hh = idx >> 5, b = idx & 31;
        g_c0T[idx] = c0[(size_t)(0 * BB + b) * HH + hh];
        g_c1T[idx] = c0[(size_t)(1 * BB + b) * HH + hh];
        store_x((bf16*)g_h0x[0], hh, b, h0[(size_t)(0 * BB + b) * HH + hh]);
        store_x((bf16*)g_h1x[0], hh, b, h0[(size_t)(1 * BB + b) * HH + hh]);
        store_x((bf16*)g_feedx, hh, b, 0.f);
    }
}

// ---------------- launcher (graph-capturable: kernel launches only) ----------------
extern "C" void kernel_launch(void* const* d_in, const int* in_sizes, int n_in,
                              void* d_out, int out_size) {
    const int*   ids   = (const int*)  d_in[0];
    const float* ctx   = (const float*)d_in[1];
    const int*   lens  = (const int*)  d_in[2];
    const float* h0    = (const float*)d_in[3];
    const float* c0    = (const float*)d_in[4];
    const float* emb   = (const float*)d_in[5];
    const float* W_ih0 = (const float*)d_in[6];
    const float* W_hh0 = (const float*)d_in[7];
    const float* b_ih0 = (const float*)d_in[8];
    const float* b_hh0 = (const float*)d_in[9];
    const float* W_ih1 = (const float*)d_in[10];
    const float* W_hh1 = (const float*)d_in[11];
    const float* b_ih1 = (const float*)d_in[12];
    const float* b_hh1 = (const float*)d_in[13];
    const float* W_in  = (const float*)d_in[14];
    const float* W_out = (const float*)d_in[15];

    float* outv = (float*)d_out;                      // outputs [T,B,H]
    float* attn = outv + (size_t)TT * BB * HH;        // attns   [T,B,S]

    // 3 setup launches, then k_seq
    k_wconvAll<<<dim3(256, 128, 6), 32>>>(W_ih0, W_hh0, W_ih1, W_hh1, W_in, W_out);
    k_embx_init<<<256, 256>>>(ids, emb, ctx, h0, c0);
    k_progemm<<<dim3(32, 16, 2), 256>>>();

    k_seq<<<NBLK, 256>>>(ctx, lens, b_ih0, b_hh0, b_ih1, b_hh1, outv, attn);
}

// round 17
// speedup vs baseline: 1.6393x; 1.5354x over previous
#include <cuda_runtime.h>
#include <cuda_bf16.h>
#include <math.h>
#include <stdint.h>

#define TT 64
#define BB 32
#define SS 64
#define HH 1024
#define NBLK 128

typedef __nv_bfloat16 bf16;

// ---------------- static device scratch (no allocations) ----------------
// Weight fragments (uint32): [rowtile16][kstep][sel hi/lo][lane(32)][reg(4)]
// gates use gate-permuted rows: rt pair per block, pib=(rt&1)*16+i, gate=pib>>3.
__device__ uint32_t g_w0[(size_t)256 * 192 * 2 * 128];  // ks 0-63 ih0-emb, 64-127 ih0-feed, 128-191 hh0
__device__ uint32_t g_w1[(size_t)256 * 128 * 2 * 128];  // ks 0-63 ih1(h0), 64-127 hh1(h1)
__device__ uint32_t g_wq[(size_t)64 * 64 * 2 * 128];    // W_in
__device__ uint32_t g_wo[(size_t)64 * 128 * 2 * 128];   // W_out: ks 0-63 cvec, 64-127 h1

// Activation B-fragments: per 1024-k vector: [kstep(64)][sel(2)][ntile(4)][lane(32)][reg(2)]
__device__ uint32_t g_embx[(size_t)TT * 32768];
__device__ uint32_t g_h0x[2][32768];   // double-buffered
__device__ uint32_t g_h1x[2][32768];
__device__ uint32_t g_feedx[32768];
__device__ uint32_t g_cvx[32768];

__device__ float g_ge[(size_t)TT * 4096 * 32];  // W_ih0_emb @ emb_t (fragment-row order)
__device__ float g_c0T[HH * BB];                // [hh][b]
__device__ float g_c1T[HH * BB];
__device__ float g_qf[HH * BB];                 // [b][row]

// epoch flags (32B padded, monotonic)
__device__ unsigned g_barA[128 * 8];
__device__ unsigned g_barB[128 * 8];
__device__ unsigned g_flagQ[64 * 8];
__device__ unsigned g_flagCV[32 * 8];
__device__ unsigned g_flagF[64 * 8];

// ---------------- helpers ----------------
__device__ __forceinline__ float sigm(float x) { return 1.f / (1.f + expf(-x)); }

__device__ __forceinline__ void store_x(bf16* base, int hh, int b, float v) {
    int kstep = hh >> 4, kk = hh & 15;
    int ntile = b >> 3, gid = b & 7;
    int reg = kk >> 3, krem = kk & 7, tig = krem >> 1, half = krem & 1;
    int lane = gid * 4 + tig;
    bf16 hi = __float2bfloat16(v);
    bf16 lo = __float2bfloat16(v - __bfloat162float(hi));
    size_t i0 = ((((size_t)kstep * 2 + 0) * 4 + ntile) * 64 + lane * 2 + reg) * 2 + half;
    size_t i1 = ((((size_t)kstep * 2 + 1) * 4 + ntile) * 64 + lane * 2 + reg) * 2 + half;
    base[i0] = hi;
    base[i1] = lo;
}

__device__ __forceinline__ void mma_bf16(float* d, const uint32_t* a, uint32_t b0, uint32_t b1) {
    asm volatile(
        "mma.sync.aligned.m16n8k16.row.col.f32.bf16.bf16.f32 "
        "{%0,%1,%2,%3}, {%4,%5,%6,%7}, {%8,%9}, {%0,%1,%2,%3};"
        : "+f"(d[0]), "+f"(d[1]), "+f"(d[2]), "+f"(d[3])
        : "r"(a[0]), "r"(a[1]), "r"(a[2]), "r"(a[3]), "r"(b0), "r"(b1));
}

__device__ __forceinline__ void flag_set(unsigned* f, int slot, unsigned e) {
    __syncthreads();
    __threadfence();
    if (threadIdx.x == 0) atomicExch(&f[slot * 8], e);
}
__device__ __forceinline__ void flags_wait(unsigned* f, int n, unsigned e) {
    if ((int)threadIdx.x < n)
        while (__ldcg(&f[threadIdx.x * 8]) < e) __nanosleep(32);
    __syncthreads();
    __threadfence();
}
// warp-scope: each lane polls 2 of the 64 feed flags
__device__ __forceinline__ void warp_wait_feed(unsigned e, int lane) {
    while (__ldcg(&g_flagF[lane * 8]) < e || __ldcg(&g_flagF[(lane + 32) * 8]) < e)
        __nanosleep(32);
    __syncwarp();
    __threadfence();
}

// 2-rowtile warp GEMM: B loaded once per kstep, used for rt0 and rt0+1.
__device__ __forceinline__ void warp_gemm2(
    const uint32_t* __restrict__ Wt, int nk, int rt0, int k0, int kn, int split,
    const uint32_t* __restrict__ xlo, const uint32_t* __restrict__ xhi,
    float acc[2][4][4], int lane)
{
    const uint4* A0 = (const uint4*)Wt + ((size_t)rt0 * nk + k0) * 64 + lane;
    const uint4* A1 = (const uint4*)Wt + ((size_t)(rt0 + 1) * nk + k0) * 64 + lane;
    #pragma unroll 4
    for (int s = 0; s < kn; s++) {
        int ks = k0 + s;
        const uint32_t* xs = (ks < split) ? xlo : xhi;
        const uint2* xb = (const uint2*)(xs + (size_t)(ks & 63) * 512);
        uint2 bh[4], bl[4];
        #pragma unroll
        for (int nt = 0; nt < 4; nt++) {
            bh[nt] = __ldcg(&xb[nt * 32 + lane]);
            bl[nt] = __ldcg(&xb[128 + nt * 32 + lane]);
        }
        uint4 ah0 = __ldg(A0), al0 = __ldg(A0 + 32);
        uint4 ah1 = __ldg(A1), al1 = __ldg(A1 + 32);
        A0 += 64; A1 += 64;
        #pragma unroll
        for (int nt = 0; nt < 4; nt++) {
            mma_bf16(acc[0][nt], (const uint32_t*)&ah0, bh[nt].x, bh[nt].y);
            mma_bf16(acc[0][nt], (const uint32_t*)&ah0, bl[nt].x, bl[nt].y);
            mma_bf16(acc[0][nt], (const uint32_t*)&al0, bh[nt].x, bh[nt].y);
            mma_bf16(acc[1][nt], (const uint32_t*)&ah1, bh[nt].x, bh[nt].y);
            mma_bf16(acc[1][nt], (const uint32_t*)&ah1, bl[nt].x, bl[nt].y);
            mma_bf16(acc[1][nt], (const uint32_t*)&al1, bh[nt].x, bh[nt].y);
        }
    }
}

// 1-rowtile warp GEMM (q / wo)
__device__ __forceinline__ void warp_gemm1(
    const uint32_t* __restrict__ Wt, int nk, int rt, int k0, int kn,
    const uint32_t* __restrict__ xlo, const uint32_t* __restrict__ xhi,
    float acc[4][4], int lane)
{
    const uint4* Ap = (const uint4*)Wt + ((size_t)rt * nk + k0) * 64 + lane;
    #pragma unroll 4
    for (int s = 0; s < kn; s++) {
        int ks = k0 + s;
        const uint32_t* xs = (ks < 64) ? xlo : xhi;
        const uint2* xb = (const uint2*)(xs + (size_t)(ks & 63) * 512);
        uint2 bh[4], bl[4];
        #pragma unroll
        for (int nt = 0; nt < 4; nt++) {
            bh[nt] = __ldcg(&xb[nt * 32 + lane]);
            bl[nt] = __ldcg(&xb[128 + nt * 32 + lane]);
        }
        uint4 ah = __ldg(Ap), al = __ldg(Ap + 32);
        Ap += 64;
        #pragma unroll
        for (int nt = 0; nt < 4; nt++) {
            mma_bf16(acc[nt], (const uint32_t*)&ah, bh[nt].x, bh[nt].y);
            mma_bf16(acc[nt], (const uint32_t*)&ah, bl[nt].x, bl[nt].y);
            mma_bf16(acc[nt], (const uint32_t*)&al, bh[nt].x, bh[nt].y);
        }
    }
}

// red layout: red[(w*2 + rti)*512 + row16*32 + b], 16 warps
__device__ __forceinline__ void acc_to_red(float* red, const float acc[4][4], int lane) {
    int gid = lane >> 2, tig = lane & 3;
    #pragma unroll
    for (int nt = 0; nt < 4; nt++) {
        int c = nt * 8 + tig * 2;
        red[gid * 32 + c]           = acc[nt][0];
        red[gid * 32 + c + 1]       = acc[nt][1];
        red[(gid + 8) * 32 + c]     = acc[nt][2];
        red[(gid + 8) * 32 + c + 1] = acc[nt][3];
    }
}

// LSTM cell tail (16-warp reduction): block covers hh [8*bid, 8*bid+8).
// Only threads 0..255 participate (caller must NOT syncthreads-diverge).
__device__ __forceinline__ void cell_tail16(const float* __restrict__ red,
                                            const float* __restrict__ bih,
                                            const float* __restrict__ bhh,
                                            float* __restrict__ cT, uint32_t* __restrict__ hx,
                                            const float* __restrict__ ge,
                                            int bid, int tid)
{
    if (tid >= 256) return;
    int hl = tid >> 5, bb = tid & 31;
    float gv[4];
    #pragma unroll
    for (int gt = 0; gt < 4; gt++) {
        int pib = gt * 8 + hl;
        int par = pib >> 4;
        int idx = (pib & 15) * 32 + bb;
        float s = 0.f;
        #pragma unroll
        for (int kc = 0; kc < 16; kc++) s += red[(kc * 2 + par) * 512 + idx];
        if (ge) s += __ldg(&ge[(size_t)(bid * 32 + pib) * 32 + bb]);
        gv[gt] = s;
    }
    int hh = bid * 8 + hl;
    float gi = gv[0] + bih[hh]            + bhh[hh];
    float gf = gv[1] + bih[1024 + hh]     + bhh[1024 + hh];
    float gg = gv[2] + bih[2048 + hh]     + bhh[2048 + hh];
    float go = gv[3] + bih[3072 + hh]     + bhh[3072 + hh];
    int e = hh * 32 + bb;
    float cn = sigm(gf) * cT[e] + sigm(gi) * tanhf(gg);
    cT[e] = cn;
    store_x((bf16*)hx, hh, bb, sigm(go) * tanhf(cn));
}

// ---------------- persistent sequence kernel: 512 threads (16 warps, 4/SMSP) ----------------
__global__ void __launch_bounds__(512, 1)
k_seq(const float* __restrict__ ctx, const int* __restrict__ lens,
      const float* __restrict__ bih0, const float* __restrict__ bhh0,
      const float* __restrict__ bih1, const float* __restrict__ bhh1,
      float* __restrict__ outv, float* __restrict__ attnout)
{
    extern __shared__ float red[];   // [16][2][512] = 64KB
    __shared__ float sc[SS];
    int tid = threadIdx.x, w = tid >> 5, lane = tid & 31;
    int bid = blockIdx.x;

    for (int t = 0; t < TT; t++) {
        unsigned ep = (unsigned)t + 1u;
        int p = t & 1;
        const uint32_t* h0o = g_h0x[p];
        uint32_t*       h0n = g_h0x[p ^ 1];
        const uint32_t* h1o = g_h1x[p];
        uint32_t*       h1n = g_h1x[p ^ 1];

        // ---- P1: gates0. h0-half first (no wait), then feed-half after flagF(t-1) ----
        {
            float acc[2][4][4] = {};
            warp_gemm2(g_w0, 192, bid * 2, 128 + w * 4, 4, 128, g_feedx, h0o, acc, lane);
            warp_wait_feed((unsigned)t, lane);
            warp_gemm2(g_w0, 192, bid * 2, 64 + w * 4, 4, 128, g_feedx, h0o, acc, lane);
            acc_to_red(&red[(w * 2 + 0) * 512], acc[0], lane);
            acc_to_red(&red[(w * 2 + 1) * 512], acc[1], lane);
            __syncthreads();
            cell_tail16(red, bih0, bhh0, g_c0T, h0n, g_ge + (size_t)t * 4096 * 32, bid, tid);
        }
        flag_set(g_barA, bid, ep);
        flags_wait(g_barA, 128, ep);

        // ---- P2: gates1 (h0n ks0-63, h1o ks64-127) + cell1 ----
        {
            float acc[2][4][4] = {};
            warp_gemm2(g_w1, 128, bid * 2, w * 8, 8, 64, h0n, h1o, acc, lane);
            acc_to_red(&red[(w * 2 + 0) * 512], acc[0], lane);
            acc_to_red(&red[(w * 2 + 1) * 512], acc[1], lane);
            __syncthreads();
            cell_tail16(red, bih1, bhh1, g_c1T, h1n, nullptr, bid, tid);
        }
        flag_set(g_barB, bid, ep);
        flags_wait(g_barB, 128, ep);

        // ---- P3: q (blocks 0-63; 32-63 continue into attention) | wo (blocks 64-127) ----
        if (bid < 64) {
            float acc1[4][4] = {};
            warp_gemm1(g_wq, 64, bid, w * 4, 4, h1n, h1n, acc1, lane);
            acc_to_red(&red[(w * 2 + 0) * 512], acc1, lane);
            __syncthreads();
            {
                int i = tid;                       // 512 items = 16 rows x 32 b
                float s = 0.f;
                #pragma unroll
                for (int ww = 0; ww < 16; ww++) s += red[(ww * 2 + 0) * 512 + i];
                int row = bid * 16 + (i >> 5), bb = i & 31;
                g_qf[(size_t)bb * HH + row] = s;
            }
            flag_set(g_flagQ, bid, ep);

            if (bid >= 32) {
                flags_wait(g_flagQ, 64, ep);
                int b = bid - 32;
                float* qs = red;                   // 1024 floats
                for (int i = tid; i < HH; i += 512)
                    qs[i] = __ldcg(&g_qf[(size_t)b * HH + i]);
                __syncthreads();

                #pragma unroll
                for (int si = 0; si < 4; si++) {   // 16 warps x 4 scores
                    int s = w * 4 + si;
                    const float* cr = ctx + ((size_t)s * BB + b) * HH;
                    float sum = 0.f;
                    for (int i = lane; i < HH; i += 32) sum = fmaf(qs[i], __ldg(&cr[i]), sum);
                    #pragma unroll
                    for (int o = 16; o > 0; o >>= 1) sum += __shfl_xor_sync(0xffffffffu, sum, o);
                    if (lane == 0) sc[s] = sum;
                }
                __syncthreads();

                if (tid == 0) {
                    int len = lens[b];
                    len = len < 1 ? 1 : (len > SS ? SS : len);
                    float m = sc[0];
                    for (int s = 1; s < len; s++) m = fmaxf(m, sc[s]);
                    float sum = 0.f;
                    for (int s = 0; s < len; s++) { float e = expf(sc[s] - m); sc[s] = e; sum += e; }
                    float inv = 1.f / sum;
                    for (int s = 0; s < len; s++) sc[s] *= inv;
                    for (int s = len; s < SS; s++) sc[s] = 0.f;
                }
                __syncthreads();

                if (tid < SS) attnout[((size_t)t * BB + b) * SS + tid] = sc[tid];

                #pragma unroll
                for (int j = 0; j < 2; j++) {
                    int hh = tid + j * 512;
                    float a = 0.f;
                    for (int s = 0; s < SS; s++)
                        a = fmaf(sc[s], __ldg(&ctx[((size_t)s * BB + b) * HH + hh]), a);
                    store_x((bf16*)g_cvx, hh, b, a);
                }
                flag_set(g_flagCV, b, ep);
            }
        } else {
            int rt = bid - 64;
            float acc1[4][4] = {};
            warp_gemm1(g_wo, 128, rt, 64 + w * 4, 4, g_cvx, h1n, acc1, lane);  // h1 half
            flags_wait(g_flagCV, 32, ep);
            warp_gemm1(g_wo, 128, rt, w * 4, 4, g_cvx, h1n, acc1, lane);       // cvec half
            acc_to_red(&red[(w * 2 + 0) * 512], acc1, lane);
            __syncthreads();
            {
                int i = tid;                       // 512 items
                float v = 0.f;
                #pragma unroll
                for (int ww = 0; ww < 16; ww++) v += red[(ww * 2 + 0) * 512 + i];
                v = tanhf(v);
                int hh = rt * 16 + (i >> 5), bb = i & 31;
                outv[((size_t)t * BB + bb) * HH + hh] = v;
                store_x((bf16*)g_feedx, hh, bb, v);
            }
            flag_set(g_flagF, rt, ep);
        }
    }
}

// ---------------- prologue: gates0 emb contribution for ALL t ----------------
__global__ void __launch_bounds__(256, 1)
k_embgemm() {
    __shared__ uint32_t stage[4][512];
    int tid = threadIdx.x, w = tid >> 5, lane = tid & 31;
    int Mb = blockIdx.x, tg = blockIdx.y;
    int rt = Mb * 8 + w;

    float acc[4][4][4] = {};
    const uint4* Ap = (const uint4*)g_w0 + ((size_t)rt * 192) * 64 + lane;

    for (int ks = 0; ks < 64; ks++) {
        __syncthreads();
        #pragma unroll
        for (int j = 0; j < 8; j++) {
            int u = tid + j * 256;
            stage[u >> 9][u & 511] =
                __ldg(&g_embx[(size_t)(tg * 4 + (u >> 9)) * 32768 + (size_t)ks * 512 + (u & 511)]);
        }
        __syncthreads();
        uint4 ah = __ldg(Ap), al = __ldg(Ap + 32);
        Ap += 64;
        #pragma unroll
        for (int tt = 0; tt < 4; tt++) {
            const uint2* xb = (const uint2*)stage[tt];
            #pragma unroll
            for (int nt = 0; nt < 4; nt++) {
                uint2 bh = xb[nt * 32 + lane];
                uint2 bl = xb[128 + nt * 32 + lane];
                mma_bf16(acc[tt][nt], (const uint32_t*)&ah, bh.x, bh.y);
                mma_bf16(acc[tt][nt], (const uint32_t*)&ah, bl.x, bl.y);
                mma_bf16(acc[tt][nt], (const uint32_t*)&al, bh.x, bh.y);
            }
        }
    }

    int gid = lane >> 2, tig = lane & 3;
    #pragma unroll
    for (int tt = 0; tt < 4; tt++) {
        float* gp = g_ge + ((size_t)(tg * 4 + tt) * 4096) * 32;
        #pragma unroll
        for (int nt = 0; nt < 4; nt++) {
            int row0 = rt * 16 + gid, col = nt * 8 + tig * 2;
            *(float2*)&gp[(size_t)row0 * 32 + col] = make_float2(acc[tt][nt][0], acc[tt][nt][1]);
            *(float2*)&gp[(size_t)(row0 + 8) * 32 + col] = make_float2(acc[tt][nt][2], acc[tt][nt][3]);
        }
    }
}

// ---------------- weight conversion ----------------
__device__ __forceinline__ void wconv_one(const float* __restrict__ W, int ldw,
                                          uint32_t* __restrict__ dst, int nkTot, int ksBase,
                                          int gatePerm, int rt, int ks) {
    int lane = threadIdx.x;
    int gid = lane >> 2, tig = lane & 3;
    uint32_t hi[4], lo[4];
    #pragma unroll
    for (int r = 0; r < 4; r++) {
        int i = gid + (r & 1) * 8;
        int row;
        if (gatePerm) {
            int pib = (rt & 1) * 16 + i;
            int gate = pib >> 3, hho = pib & 7;
            row = gate * 1024 + (rt >> 1) * 8 + hho;
        } else {
            row = rt * 16 + i;
        }
        int kk = ks * 16 + (r >> 1) * 8 + tig * 2;
        float w0 = __ldg(&W[(size_t)row * ldw + kk]);
        float w1 = __ldg(&W[(size_t)row * ldw + kk + 1]);
        bf16 h0 = __float2bfloat16(w0), h1 = __float2bfloat16(w1);
        bf16 l0 = __float2bfloat16(w0 - __bfloat162float(h0));
        bf16 l1 = __float2bfloat16(w1 - __bfloat162float(h1));
        hi[r] = ((uint32_t)__bfloat16_as_ushort(h1) << 16) | __bfloat16_as_ushort(h0);
        lo[r] = ((uint32_t)__bfloat16_as_ushort(l1) << 16) | __bfloat16_as_ushort(l0);
    }
    size_t bi = (((size_t)rt * nkTot + ksBase + ks) * 2) * 128 + lane * 4;
    #pragma unroll
    for (int r = 0; r < 4; r++) {
        dst[bi + r] = hi[r];
        dst[bi + 128 + r] = lo[r];
    }
}

__global__ void k_wconvAll(const float* ih0, const float* hh0, const float* ih1,
                           const float* hh1, const float* win, const float* wout) {
    int rt = blockIdx.x, ks = blockIdx.y, z = blockIdx.z;
    switch (z) {
        case 0: wconv_one(ih0, 2048, g_w0, 192, 0, 1, rt, ks); break;                 // ks<128
        case 1: if (ks < 64) wconv_one(hh0, 1024, g_w0, 192, 128, 1, rt, ks); break;
        case 2: if (ks < 64) wconv_one(ih1, 1024, g_w1, 128, 0,   1, rt, ks); break;
        case 3: if (ks < 64) wconv_one(hh1, 1024, g_w1, 128, 64,  1, rt, ks); break;
        case 4: if (rt < 64 && ks < 64) wconv_one(win,  1024, g_wq, 64,  0, 0, rt, ks); break;
        default: if (rt < 64) wconv_one(wout, 2048, g_wo, 128, 0, 0, rt, ks); break;  // ks<128
    }
}

// ---------------- embx + init ----------------
__global__ void k_embx_init(const int* __restrict__ ids, const float* __restrict__ emb,
                            const float* __restrict__ h0, const float* __restrict__ c0) {
    int tid = threadIdx.x;
    int bid = blockIdx.x;
    if (bid < 64) {
        int t = bid;
        int b = tid & 31;
        int id = ids[t * BB + b];
        bf16* dstx = (bf16*)(g_embx + (size_t)t * 32768);
        const float* src = emb + (size_t)id * HH;
        for (int hh = tid >> 5; hh < HH; hh += 8)
            store_x(dstx, hh, b, __ldg(&src[hh]));
    } else {
        int idx = (bid - 64) * 256 + tid;
        if (idx < 128 * 8) { g_barA[idx] = 0u; g_barB[idx] = 0u; }
        if (idx < 64 * 8)  { g_flagQ[idx] = 0u; g_flagF[idx] = 0u; }
        if (idx < 32 * 8)  { g_flagCV[idx] = 0u; }
        if (idx >= HH * BB) return;
        int hh = idx >> 5, b = idx & 31;
        g_c0T[idx] = c0[(size_t)(0 * BB + b) * HH + hh];
        g_c1T[idx] = c0[(size_t)(1 * BB + b) * HH + hh];
        store_x((bf16*)g_h0x[0], hh, b, h0[(size_t)(0 * BB + b) * HH + hh]);
        store_x((bf16*)g_h1x[0], hh, b, h0[(size_t)(1 * BB + b) * HH + hh]);
        store_x((bf16*)g_feedx, hh, b, 0.f);
    }
}

// ---------------- launcher (graph-capturable: kernel launches only) ----------------
extern "C" void kernel_launch(void* const* d_in, const int* in_sizes, int n_in,
                              void* d_out, int out_size) {
    const int*   ids   = (const int*)  d_in[0];
    const float* ctx   = (const float*)d_in[1];
    const int*   lens  = (const int*)  d_in[2];
    const float* h0    = (const float*)d_in[3];
    const float* c0    = (const float*)d_in[4];
    const float* emb   = (const float*)d_in[5];
    const float* W_ih0 = (const float*)d_in[6];
    const float* W_hh0 = (const float*)d_in[7];
    const float* b_ih0 = (const float*)d_in[8];
    const float* b_hh0 = (const float*)d_in[9];
    const float* W_ih1 = (const float*)d_in[10];
    const float* W_hh1 = (const float*)d_in[11];
    const float* b_ih1 = (const float*)d_in[12];
    const float* b_hh1 = (const float*)d_in[13];
    const float* W_in  = (const float*)d_in[14];
    const float* W_out = (const float*)d_in[15];

    float* outv = (float*)d_out;                      // outputs [T,B,H]
    float* attn = outv + (size_t)TT * BB * HH;        // attns   [T,B,S]

    static int smem_set = 0;
    if (!smem_set) {
        cudaFuncSetAttribute(k_seq, cudaFuncAttributeMaxDynamicSharedMemorySize, 66000);
        smem_set = 1;
    }

    // 3 setup launches, then k_seq (captured by ncu -s 5 -c 1)
    k_wconvAll<<<dim3(256, 128, 6), 32>>>(W_ih0, W_hh0, W_ih1, W_hh1, W_in, W_out);
    k_embx_init<<<192, 256>>>(ids, emb, h0, c0);
    k_embgemm<<<dim3(32, 16), 256>>>();

    k_seq<<<NBLK, 512, 65536>>>(ctx, lens, b_ih0, b_hh0, b_ih1, b_hh1, outv, attn);
}